// round 10
// baseline (speedup 1.0000x reference)
#include <cuda_runtime.h>
#include <math.h>
#include <cstdint>

// Problem constants
#define HD   96
#define WD   96
// tile
#define PXB  8      // pixels (w) per block
#define ROWS 4      // output rows per block
#define XW   16     // halo window cols [w0-4, w0+12), 4-aligned
#define CHS  130    // channel stride in floats (even -> float2-aligned for all lanes)

// shared layout (floats)
#define IN_SH_F   (128*CHS)          // 16640
#define CONV_SH_F (PXB*32*36)        // 9216 : conv[p][o*8+j][z] ; reused as out staging 256x9
#define MP_SH_F   512                // [o][t][bb][k]  (k contiguous -> LDS.128)
#define MA_PAD    16
#define MA_SH_F   512
#define MB_SH_F   128
#define SMEM_F (IN_SH_F + CONV_SH_F + MP_SH_F + MA_PAD + MA_SH_F + MB_SH_F)

// conv weights live in constant memory: warp-uniform addresses -> constant port, off L1
__constant__ __align__(16) float cWc[800];
// prep scratch: [0:512) mp normalized+relayout, [512:1024) ma relayout, [1024:1152) mb
__device__ float g_prep[1152];

// Blackwell packed fp32 ops (b64 register pairs)
#define FMA_F32X2(d, a, b, c) \
    asm("fma.rn.f32x2 %0, %1, %2, %3;" : "=l"(d) : "l"(a), "l"(b), "l"(c))
#define PACK_DUP_F32X2(d, v) \
    asm("mov.b64 %0, {%1, %1};" : "=l"(d) : "f"(v))
#define UNPACK_F32X2(lo, hi, in) \
    asm("mov.b64 {%0, %1}, %2;" : "=f"(lo), "=f"(hi) : "l"(in))

__global__ void prep_kernel(const float* __restrict__ Wp,
                            const float* __restrict__ Wa,
                            const float* __restrict__ ba)
{
    int tid = threadIdx.x;
    // relayout [o][t][bb][k]; mp column-normalized over k
    {
        int q8 = tid >> 4;           // o*8 + t
        int bb = (tid >> 2) & 3;
        int k  = tid & 3;
        int o  = q8 >> 3, t = q8 & 7;
        int src = o*128 + t*16 + k*4 + bb;
        float s = 0.f;
        #pragma unroll
        for (int kk = 0; kk < 4; kk++) {
            float v = Wp[o*128 + t*16 + kk*4 + bb];
            s += v * v;
        }
        float nrm = sqrtf(fmaxf(s, 1e-12f));
        g_prep[tid]       = Wp[src] / nrm;
        g_prep[512 + tid] = Wa[src];
    }
    // folded app bias: mb[(o*8+t)*4+bb] = ba[o,t] * sum_k Wa[o,t,k,bb]
    if (tid < 128) {
        int bb = tid & 3, t = (tid >> 2) & 7, o = tid >> 5;
        float sm = 0.f;
        #pragma unroll
        for (int k = 0; k < 4; k++) sm += Wa[o*128 + t*16 + k*4 + bb];
        g_prep[1024 + tid] = ba[o*8 + t] * sm;
    }
}

__global__ void __launch_bounds__(512, 2)
caps2d_fused_kernel(const float* __restrict__ inp,
                    float* __restrict__ out)
{
    extern __shared__ float smem[];
    float* in_sh   = smem;
    float* conv_sh = in_sh + IN_SH_F;
    float* mp_sh   = conv_sh + CONV_SH_F;
    float* ma_sh   = mp_sh + MP_SH_F + MA_PAD;
    float* mb_sh   = ma_sh + MA_SH_F;

    const int tid  = threadIdx.x;
    const int warp = tid >> 5;
    const int lane = tid & 31;
    const int w0   = blockIdx.x * PXB;
    const int hh0  = blockIdx.y * ROWS;
    const int n    = blockIdx.z;

    // ---- copy prepped matrices to smem ----
    mp_sh[tid] = g_prep[tid];
    ma_sh[tid] = g_prep[512 + tid];
    if (tid < 128) mb_sh[tid] = g_prep[1024 + tid];

    // ---- vector halo load: 8 rows x 16 cols x 128 ch ----
    {
        int id  = tid & 31;          // (y,g)
        int y   = id >> 2;           // 0..7
        int g   = id & 3;            // float4 group
        int ch0 = tid >> 5;          // 0..15 ; ch = ch0 + 16*c
        int gy  = hh0 - 2 + y;
        int gx0 = w0 - 4 + g*4;
        bool ok = (gy >= 0) && (gy < HD) && (gx0 >= 0) && (gx0 + 3 < WD);
        const float* src = inp + ((n*128 + ch0)*HD + gy)*WD + gx0;
        float* dst = in_sh + ch0*CHS + y*XW + g*4;
        #pragma unroll
        for (int c = 0; c < 8; c++) {
            float4 v = make_float4(0.f, 0.f, 0.f, 0.f);
            if (ok) v = *reinterpret_cast<const float4*>(src);
            dst[0] = v.x; dst[1] = v.y; dst[2] = v.z; dst[3] = v.w;
            src += 16*HD*WD;
            dst += 16*CHS;
        }
    }
    __syncthreads();

    // routing-role constants
    const int half = warp & 1;
    const int p    = warp >> 1;
    const int gw   = w0 + p;
    const int a_   = (lane >> 2) & 3;
    const int bb   = lane & 3;
    const bool app = (lane >> 4) != 0;
    const float cx = (float)gw * (1.f/96.f);
    // conv-role constants
    const int o_c  = warp & 3;
    const int p0   = (warp >> 2) * 2;
    const unsigned FULL = 0xffffffffu;
    const bool x0 = (lane & 1) != 0;
    const bool x1 = (lane & 2) != 0;
    const bool x2 = (lane & 4) != 0;
    const bool x3 = (lane & 8) != 0;

    for (int hr = 0; hr < ROWS; hr++) {
        // ---- phase 1: depthwise 5x5 conv, packed f32x2 (j-pairs), weights from constant ----
        {
            uint64_t acc2[8];        // [px(2)][jpair(4)]
            #pragma unroll
            for (int q = 0; q < 8; q++) acc2[q] = 0ull;
            const float* ib = in_sh + (o_c*32 + lane)*CHS;
            #pragma unroll
            for (int ky = 0; ky < 5; ky++) {
                // 6 consecutive inputs as 3 float2 (8B aligned: CHS even, base even)
                const float2* ib2 = reinterpret_cast<const float2*>(ib + (hr + ky)*XW + p0 + 2);
                float2 q0 = ib2[0], q1 = ib2[1], q2 = ib2[2];
                float r[6] = {q0.x, q0.y, q1.x, q1.y, q2.x, q2.y};
                #pragma unroll
                for (int kx = 0; kx < 5; kx++) {
                    const ulonglong2 wA = *reinterpret_cast<const ulonglong2*>(cWc + o_c*200 + (ky*5 + kx)*8);
                    const ulonglong2 wB = *reinterpret_cast<const ulonglong2*>(cWc + o_c*200 + (ky*5 + kx)*8 + 4);
                    uint64_t va2, vb2;
                    PACK_DUP_F32X2(va2, r[kx]);
                    PACK_DUP_F32X2(vb2, r[kx + 1]);
                    FMA_F32X2(acc2[0], va2, wA.x, acc2[0]);
                    FMA_F32X2(acc2[1], va2, wA.y, acc2[1]);
                    FMA_F32X2(acc2[2], va2, wB.x, acc2[2]);
                    FMA_F32X2(acc2[3], va2, wB.y, acc2[3]);
                    FMA_F32X2(acc2[4], vb2, wA.x, acc2[4]);
                    FMA_F32X2(acc2[5], vb2, wA.y, acc2[5]);
                    FMA_F32X2(acc2[6], vb2, wB.x, acc2[6]);
                    FMA_F32X2(acc2[7], vb2, wB.y, acc2[7]);
                }
            }
            float* c0 = conv_sh + p0*(32*36)       + (o_c*8)*36 + lane;
            float* c1 = conv_sh + (p0 + 1)*(32*36) + (o_c*8)*36 + lane;
            #pragma unroll
            for (int jp = 0; jp < 4; jp++) {
                float lo, hi;
                UNPACK_F32X2(lo, hi, acc2[jp]);
                c0[(2*jp)*36]     = lo;
                c0[(2*jp + 1)*36] = hi;
            }
            #pragma unroll
            for (int jp = 0; jp < 4; jp++) {
                float lo, hi;
                UNPACK_F32X2(lo, hi, acc2[4 + jp]);
                c1[(2*jp)*36]     = lo;
                c1[(2*jp + 1)*36] = hi;
            }
        }
        __syncthreads();   // conv_sh ready; role swap

        // ---- phase 2: u_hat[z=lane][q = o*4+tt] ----
        const float cy = (float)(hh0 + hr) * (1.f/96.f);
        float* csh = conv_sh + p * (32*36);
        float uh[16];
        #pragma unroll
        for (int o = 0; o < 4; o++) {
            #pragma unroll
            for (int tt = 0; tt < 4; tt++) {
                const int t  = half*4 + tt;
                const int j  = (app ? 4 : 0) + (t >> 1);
                const int zb = ((t & 1) << 4) + (a_ << 2);
                const float4 cv = *reinterpret_cast<const float4*>(csh + (o*8 + j)*36 + zb);
                const float* msrc = (app ? ma_sh : mp_sh) + ((o*8 + t)*4 + bb)*4;
                float4 m = *reinterpret_cast<const float4*>(msrc);
                float s0 = 0.f;
                if (app) {
                    s0 = mb_sh[(o*8 + t)*4 + bb];
                } else {
                    if (bb == 0)      m.w += cx;
                    else if (bb == 1) m.w += cy;
                }
                float s;
                s = fmaf(cv.x, m.x, s0);
                s = fmaf(cv.y, m.y, s);
                s = fmaf(cv.z, m.z, s);
                s = fmaf(cv.w, m.w, s);
                uh[o*4 + tt] = s;
            }
        }

        // ---- phase 3: dynamic routing ----
        float bq = 0.f;
        float v_[4];
        for (int iter = 0; iter < 3; iter++) {
            float pt[4];
            if (iter == 0) {
                #pragma unroll
                for (int tt = 0; tt < 4; tt++)
                    pt[tt] = 0.5f * (uh[tt] + uh[4 + tt] + uh[8 + tt] + uh[12 + tt]);
            } else {
                float rq = 1.f / (1.f + __expf(-bq));
                #pragma unroll
                for (int tt = 0; tt < 4; tt++) {
                    float s = 0.f;
                    #pragma unroll
                    for (int o = 0; o < 4; o++) {
                        float r = __shfl_sync(FULL, rq, (lane & 16) | (o*4 + tt));
                        s = fmaf(uh[o*4 + tt], r, s);
                    }
                    pt[tt] = s;
                }
            }
            #pragma unroll
            for (int tt = 0; tt < 4; tt++) {
                float x = app ? pt[tt]*pt[tt] : fabsf(pt[tt]);
                #pragma unroll
                for (int d = 1; d < 16; d <<= 1) {
                    float y = __shfl_xor_sync(FULL, x, d);
                    x = app ? (x + y) : fmaxf(x, y);
                }
                if (app) {
                    v_[tt] = x / (1.f + x) * pt[tt] * rsqrtf(x + 1e-9f);
                } else {
                    v_[tt] = pt[tt] / x;
                }
            }
            if (iter == 2) break;

            // multi-value butterfly, 15+1 shfl
            float t8[8];
            #pragma unroll
            for (int j = 0; j < 8; j++) {
                float sa = uh[2*j]     * v_[(2*j)     & 3];
                float sb = uh[2*j + 1] * v_[(2*j + 1) & 3];
                float keep = x0 ? sb : sa;
                float send = x0 ? sa : sb;
                t8[j] = keep + __shfl_xor_sync(FULL, send, 1);
            }
            float t4[4];
            #pragma unroll
            for (int j = 0; j < 4; j++) {
                float keep = x1 ? t8[2*j + 1] : t8[2*j];
                float send = x1 ? t8[2*j]     : t8[2*j + 1];
                t4[j] = keep + __shfl_xor_sync(FULL, send, 2);
            }
            float t2[2];
            #pragma unroll
            for (int j = 0; j < 2; j++) {
                float keep = x2 ? t4[2*j + 1] : t4[2*j];
                float send = x2 ? t4[2*j]     : t4[2*j + 1];
                t2[j] = keep + __shfl_xor_sync(FULL, send, 4);
            }
            {
                float keep = x3 ? t2[1] : t2[0];
                float send = x3 ? t2[0] : t2[1];
                float R = keep + __shfl_xor_sync(FULL, send, 8);
                float other = __shfl_xor_sync(FULL, R, 16);
                bq = fmaf(R, other, bq);
            }
        }

        __syncthreads();   // all conv_sh reads done -> reuse as out staging

        // ---- stage: os[row][px], row = (half*4+tt)*32+lane, stride 9 ----
        #pragma unroll
        for (int tt = 0; tt < 4; tt++)
            conv_sh[((half*4 + tt)*32 + lane)*9 + p] = v_[tt];
        __syncthreads();

        // ---- coalesced writeout: warp covers 4 rows x 8 px -> 4 sectors/STG ----
        {
            int x  = tid & 7;
            int r0 = tid >> 3;      // 0..63
            const float* os = conv_sh;
            float* ob = out + n*256*(HD*WD) + (hh0 + hr)*WD + w0 + x;
            #pragma unroll
            for (int k = 0; k < 4; k++) {
                int row = r0 + 64*k;
                ob[row*(HD*WD)] = os[row*9 + x];
            }
        }
        __syncthreads();   // writeout reads done before next row's conv overwrites
    }
}

extern "C" void kernel_launch(void* const* d_in, const int* in_sizes, int n_in,
                              void* d_out, int out_size)
{
    const float* inp = (const float*)d_in[0];   // (4,4,32,96,96)
    const float* Wc  = (const float*)d_in[1];   // (4,5,5,1,8)
    const float* Wp  = (const float*)d_in[2];   // (4,16,8)
    const float* Wa  = (const float*)d_in[3];   // (4,16,8)
    const float* ba  = (const float*)d_in[4];   // (4,8)
    float* out = (float*)d_out;                 // (4,8,32,96,96)

    // conv weights -> constant memory (D2D async memcpy, graph-capturable)
    void* sym = nullptr;
    cudaGetSymbolAddress(&sym, cWc);
    cudaMemcpyAsync(sym, Wc, 800 * sizeof(float), cudaMemcpyDeviceToDevice, 0);

    // weight prep (normalization/relayout/bias-fold) once
    prep_kernel<<<1, 512>>>(Wp, Wa, ba);

    const int smem_bytes = SMEM_F * (int)sizeof(float);
    cudaFuncSetAttribute(caps2d_fused_kernel,
                         cudaFuncAttributeMaxDynamicSharedMemorySize, smem_bytes);

    dim3 grid(WD / PXB, HD / ROWS, 4);   // (12, 24, 4)
    dim3 block(512);
    caps2d_fused_kernel<<<grid, block, smem_bytes>>>(inp, out);
}

// round 11
// speedup vs baseline: 1.1236x; 1.1236x over previous
#include <cuda_runtime.h>
#include <math.h>
#include <cstdint>

// Problem constants
#define HD   96
#define WD   96
// tile
#define PXB  8      // pixels (w) per block
#define ROWS 4      // output rows per block
#define XW   16     // halo window cols [w0-4, w0+12), 4-aligned
#define CHS  129    // channel stride in floats (odd -> conflict-free lane stride)

// shared layout (floats)
#define IN_SH_F   (128*CHS)          // 16512
#define CONV_SH_F (PXB*32*36)        // 9216 : conv[p][o*8+j][z] ; epilogue: out staging 256x33
#define WC_SH_F   800                // [o][ky][kx][j]
#define MP_SH_F   512                // [o][t][bb][k]  (k contiguous -> LDS.128)
#define MA_PAD    16
#define MA_SH_F   512
#define MB_SH_F   128
#define SMEM_F (IN_SH_F + CONV_SH_F + WC_SH_F + MP_SH_F + MA_PAD + MA_SH_F + MB_SH_F)

// prep scratch: [0:512) mp normalized+relayout, [512:1024) ma relayout, [1024:1152) mb
__device__ float g_prep[1152];

// Blackwell packed fp32 ops (b64 register pairs)
#define FMA_F32X2(d, a, b, c) \
    asm("fma.rn.f32x2 %0, %1, %2, %3;" : "=l"(d) : "l"(a), "l"(b), "l"(c))
#define PACK_DUP_F32X2(d, v) \
    asm("mov.b64 %0, {%1, %1};" : "=l"(d) : "f"(v))
#define UNPACK_F32X2(lo, hi, in) \
    asm("mov.b64 {%0, %1}, %2;" : "=f"(lo), "=f"(hi) : "l"(in))

__global__ void prep_kernel(const float* __restrict__ Wp,
                            const float* __restrict__ Wa,
                            const float* __restrict__ ba)
{
    int tid = threadIdx.x;
    // relayout [o][t][bb][k]; mp column-normalized over k
    {
        int q8 = tid >> 4;           // o*8 + t
        int bb = (tid >> 2) & 3;
        int k  = tid & 3;
        int o  = q8 >> 3, t = q8 & 7;
        int src = o*128 + t*16 + k*4 + bb;
        float s = 0.f;
        #pragma unroll
        for (int kk = 0; kk < 4; kk++) {
            float v = Wp[o*128 + t*16 + kk*4 + bb];
            s += v * v;
        }
        float nrm = sqrtf(fmaxf(s, 1e-12f));
        g_prep[tid]       = Wp[src] / nrm;
        g_prep[512 + tid] = Wa[src];
    }
    // folded app bias: mb[(o*8+t)*4+bb] = ba[o,t] * sum_k Wa[o,t,k,bb]
    if (tid < 128) {
        int bb = tid & 3, t = (tid >> 2) & 7, o = tid >> 5;
        float sm = 0.f;
        #pragma unroll
        for (int k = 0; k < 4; k++) sm += Wa[o*128 + t*16 + k*4 + bb];
        g_prep[1024 + tid] = ba[o*8 + t] * sm;
    }
}

__global__ void __launch_bounds__(512, 2)
caps2d_fused_kernel(const float* __restrict__ inp,
                    const float* __restrict__ Wc,
                    float* __restrict__ out)
{
    extern __shared__ float smem[];
    float* in_sh   = smem;
    float* conv_sh = in_sh + IN_SH_F;
    float* wc_sh   = conv_sh + CONV_SH_F;
    float* mp_sh   = wc_sh + WC_SH_F;
    float* ma_sh   = mp_sh + MP_SH_F + MA_PAD;
    float* mb_sh   = ma_sh + MA_SH_F;

    const int tid  = threadIdx.x;
    const int warp = tid >> 5;
    const int lane = tid & 31;
    const int w0   = blockIdx.x * PXB;
    const int hh0  = blockIdx.y * ROWS;
    const int n    = blockIdx.z;

    // ---- load conv weights + prepped matrices ----
    for (int e = tid; e < 800; e += 512) wc_sh[e] = Wc[e];
    mp_sh[tid] = g_prep[tid];
    ma_sh[tid] = g_prep[512 + tid];
    if (tid < 128) mb_sh[tid] = g_prep[1024 + tid];

    // ---- vector halo load: 8 rows x 16 cols x 128 ch ----
    {
        int id  = tid & 31;          // (y,g)
        int y   = id >> 2;           // 0..7
        int g   = id & 3;            // float4 group
        int ch0 = tid >> 5;          // 0..15 ; ch = ch0 + 16*c
        int gy  = hh0 - 2 + y;
        int gx0 = w0 - 4 + g*4;
        bool ok = (gy >= 0) && (gy < HD) && (gx0 >= 0) && (gx0 + 3 < WD);
        const float* src = inp + ((n*128 + ch0)*HD + gy)*WD + gx0;
        float* dst = in_sh + ch0*CHS + y*XW + g*4;
        #pragma unroll
        for (int c = 0; c < 8; c++) {
            float4 v = make_float4(0.f, 0.f, 0.f, 0.f);
            if (ok) v = *reinterpret_cast<const float4*>(src);
            dst[0] = v.x; dst[1] = v.y; dst[2] = v.z; dst[3] = v.w;
            src += 16*HD*WD;
            dst += 16*CHS;
        }
    }
    __syncthreads();

    // routing-role constants
    const int half = warp & 1;
    const int p    = warp >> 1;
    const int gw   = w0 + p;
    const int a_   = (lane >> 2) & 3;
    const int bb   = lane & 3;
    const bool app = (lane >> 4) != 0;
    const float cx = (float)gw * (1.f/96.f);
    // conv-role constants
    const int o_c  = warp & 3;
    const int p0   = (warp >> 2) * 2;
    const unsigned FULL = 0xffffffffu;
    const bool x0 = (lane & 1) != 0;
    const bool x1 = (lane & 2) != 0;
    const bool x2 = (lane & 4) != 0;
    const bool x3 = (lane & 8) != 0;

    float vr[16];   // routing outputs, 4 per row, held to the epilogue

    #pragma unroll
    for (int hr = 0; hr < ROWS; hr++) {
        // ---- phase 1: depthwise 5x5 conv, packed f32x2 (j-pairs) ----
        {
            uint64_t acc2[8];        // [px(2)][jpair(4)]
            #pragma unroll
            for (int q = 0; q < 8; q++) acc2[q] = 0ull;
            const float* ib  = in_sh + (o_c*32 + lane)*CHS;
            const float* wcb = wc_sh + o_c*200;
            #pragma unroll
            for (int ky = 0; ky < 5; ky++) {
                float r[6];
                #pragma unroll
                for (int q = 0; q < 6; q++) r[q] = ib[(hr + ky)*XW + p0 + 2 + q];
                #pragma unroll
                for (int kx = 0; kx < 5; kx++) {
                    const ulonglong2 wA = *reinterpret_cast<const ulonglong2*>(wcb + (ky*5 + kx)*8);
                    const ulonglong2 wB = *reinterpret_cast<const ulonglong2*>(wcb + (ky*5 + kx)*8 + 4);
                    uint64_t va2, vb2;
                    PACK_DUP_F32X2(va2, r[kx]);
                    PACK_DUP_F32X2(vb2, r[kx + 1]);
                    FMA_F32X2(acc2[0], va2, wA.x, acc2[0]);
                    FMA_F32X2(acc2[1], va2, wA.y, acc2[1]);
                    FMA_F32X2(acc2[2], va2, wB.x, acc2[2]);
                    FMA_F32X2(acc2[3], va2, wB.y, acc2[3]);
                    FMA_F32X2(acc2[4], vb2, wA.x, acc2[4]);
                    FMA_F32X2(acc2[5], vb2, wA.y, acc2[5]);
                    FMA_F32X2(acc2[6], vb2, wB.x, acc2[6]);
                    FMA_F32X2(acc2[7], vb2, wB.y, acc2[7]);
                }
            }
            float* c0 = conv_sh + p0*(32*36)       + (o_c*8)*36 + lane;
            float* c1 = conv_sh + (p0 + 1)*(32*36) + (o_c*8)*36 + lane;
            #pragma unroll
            for (int jp = 0; jp < 4; jp++) {
                float lo, hi;
                UNPACK_F32X2(lo, hi, acc2[jp]);
                c0[(2*jp)*36]     = lo;
                c0[(2*jp + 1)*36] = hi;
            }
            #pragma unroll
            for (int jp = 0; jp < 4; jp++) {
                float lo, hi;
                UNPACK_F32X2(lo, hi, acc2[4 + jp]);
                c1[(2*jp)*36]     = lo;
                c1[(2*jp + 1)*36] = hi;
            }
        }
        __syncthreads();   // conv_sh ready; role swap

        // ---- phase 2: u_hat[z=lane][q = o*4+tt] ----
        const float cy = (float)(hh0 + hr) * (1.f/96.f);
        float* csh = conv_sh + p * (32*36);
        float uh[16];
        #pragma unroll
        for (int o = 0; o < 4; o++) {
            #pragma unroll
            for (int tt = 0; tt < 4; tt++) {
                const int t  = half*4 + tt;
                const int j  = (app ? 4 : 0) + (t >> 1);
                const int zb = ((t & 1) << 4) + (a_ << 2);
                const float4 cv = *reinterpret_cast<const float4*>(csh + (o*8 + j)*36 + zb);
                const float* msrc = (app ? ma_sh : mp_sh) + ((o*8 + t)*4 + bb)*4;
                float4 m = *reinterpret_cast<const float4*>(msrc);
                float s0 = 0.f;
                if (app) {
                    s0 = mb_sh[(o*8 + t)*4 + bb];
                } else {
                    if (bb == 0)      m.w += cx;
                    else if (bb == 1) m.w += cy;
                }
                float s;
                s = fmaf(cv.x, m.x, s0);
                s = fmaf(cv.y, m.y, s);
                s = fmaf(cv.z, m.z, s);
                s = fmaf(cv.w, m.w, s);
                uh[o*4 + tt] = s;
            }
        }

        // ---- phase 3: dynamic routing -> vr[hr*4 + tt] ----
        float* v_ = vr + hr*4;
        float bq = 0.f;
        for (int iter = 0; iter < 3; iter++) {
            float pt[4];
            if (iter == 0) {
                #pragma unroll
                for (int tt = 0; tt < 4; tt++)
                    pt[tt] = 0.5f * (uh[tt] + uh[4 + tt] + uh[8 + tt] + uh[12 + tt]);
            } else {
                float rq = 1.f / (1.f + __expf(-bq));
                #pragma unroll
                for (int tt = 0; tt < 4; tt++) {
                    float s = 0.f;
                    #pragma unroll
                    for (int o = 0; o < 4; o++) {
                        float r = __shfl_sync(FULL, rq, (lane & 16) | (o*4 + tt));
                        s = fmaf(uh[o*4 + tt], r, s);
                    }
                    pt[tt] = s;
                }
            }
            #pragma unroll
            for (int tt = 0; tt < 4; tt++) {
                float x = app ? pt[tt]*pt[tt] : fabsf(pt[tt]);
                #pragma unroll
                for (int d = 1; d < 16; d <<= 1) {
                    float y = __shfl_xor_sync(FULL, x, d);
                    x = app ? (x + y) : fmaxf(x, y);
                }
                if (app) {
                    v_[tt] = x / (1.f + x) * pt[tt] * rsqrtf(x + 1e-9f);
                } else {
                    v_[tt] = pt[tt] / x;
                }
            }
            if (iter == 2) break;

            // multi-value butterfly, 15+1 shfl
            float t8[8];
            #pragma unroll
            for (int j = 0; j < 8; j++) {
                float sa = uh[2*j]     * v_[(2*j)     & 3];
                float sb = uh[2*j + 1] * v_[(2*j + 1) & 3];
                float keep = x0 ? sb : sa;
                float send = x0 ? sa : sb;
                t8[j] = keep + __shfl_xor_sync(FULL, send, 1);
            }
            float t4[4];
            #pragma unroll
            for (int j = 0; j < 4; j++) {
                float keep = x1 ? t8[2*j + 1] : t8[2*j];
                float send = x1 ? t8[2*j]     : t8[2*j + 1];
                t4[j] = keep + __shfl_xor_sync(FULL, send, 2);
            }
            float t2[2];
            #pragma unroll
            for (int j = 0; j < 2; j++) {
                float keep = x2 ? t4[2*j + 1] : t4[2*j];
                float send = x2 ? t4[2*j]     : t4[2*j + 1];
                t2[j] = keep + __shfl_xor_sync(FULL, send, 4);
            }
            {
                float keep = x3 ? t2[1] : t2[0];
                float send = x3 ? t2[0] : t2[1];
                float R = keep + __shfl_xor_sync(FULL, send, 8);
                float other = __shfl_xor_sync(FULL, R, 16);
                bq = fmaf(R, other, bq);
            }
        }
        __syncthreads();   // all conv_sh reads done before next row's conv overwrites
    }

    // ---- epilogue: stage all 4 rows, conv_sh reused as os[row][hr*8+p], stride 33 ----
    #pragma unroll
    for (int hr = 0; hr < ROWS; hr++)
        #pragma unroll
        for (int tt = 0; tt < 4; tt++)
            conv_sh[((half*4 + tt)*32 + lane)*33 + hr*8 + p] = vr[hr*4 + tt];
    __syncthreads();

    // ---- coalesced writeout: 16 independent STG per thread ----
    {
        int x  = tid & 7;
        int hw = (tid >> 3) & 3;
        int r0 = tid >> 5;          // 0..15
        const float* os = conv_sh + hw*8 + x;
        float* ob = out + n*256*(HD*WD) + (hh0 + hw)*WD + w0 + x;
        #pragma unroll
        for (int k = 0; k < 16; k++) {
            int row = r0 + 16*k;
            ob[row*(HD*WD)] = os[row*33];
        }
    }
}

extern "C" void kernel_launch(void* const* d_in, const int* in_sizes, int n_in,
                              void* d_out, int out_size)
{
    const float* inp = (const float*)d_in[0];   // (4,4,32,96,96)
    const float* Wc  = (const float*)d_in[1];   // (4,5,5,1,8)
    const float* Wp  = (const float*)d_in[2];   // (4,16,8)
    const float* Wa  = (const float*)d_in[3];   // (4,16,8)
    const float* ba  = (const float*)d_in[4];   // (4,8)
    float* out = (float*)d_out;                 // (4,8,32,96,96)

    // weight prep (normalization/relayout/bias-fold) once
    prep_kernel<<<1, 512>>>(Wp, Wa, ba);

    const int smem_bytes = SMEM_F * (int)sizeof(float);
    cudaFuncSetAttribute(caps2d_fused_kernel,
                         cudaFuncAttributeMaxDynamicSharedMemorySize, smem_bytes);

    dim3 grid(WD / PXB, HD / ROWS, 4);   // (12, 24, 4)
    dim3 block(512);
    caps2d_fused_kernel<<<grid, block, smem_bytes>>>(inp, Wc, out);
}

// round 12
// speedup vs baseline: 1.1668x; 1.0384x over previous
#include <cuda_runtime.h>
#include <math.h>
#include <cstdint>

// Problem constants
#define HD   96
#define WD   96
// tile
#define PXB  8      // pixels (w) per block
#define ROWS 4      // output rows per block
#define XW   16     // halo window cols [w0-4, w0+12), 4-aligned
#define CHS  129    // channel stride in floats (odd -> conflict-free lane stride)

// shared layout (floats)
#define IN_SH_F   (128*CHS)          // 16512
#define CONV_SH_F (PXB*32*36)        // 9216 : conv[p][o*8+j][z] ; epilogue: out staging 256x33
#define WC_SH_F   800                // [o][ky][kx][j]
#define MP_SH_F   512                // [o][t][bb][k]  (k contiguous -> LDS.128)
#define MA_PAD    16
#define MA_SH_F   512
#define MB_SH_F   128
#define SMEM_F (IN_SH_F + CONV_SH_F + WC_SH_F + MP_SH_F + MA_PAD + MA_SH_F + MB_SH_F)

// prep scratch: [0:512) mp normalized+relayout, [512:1024) ma relayout, [1024:1152) mb
__device__ float g_prep[1152];

// Blackwell packed fp32 ops (b64 register pairs)
#define FMA_F32X2(d, a, b, c) \
    asm("fma.rn.f32x2 %0, %1, %2, %3;" : "=l"(d) : "l"(a), "l"(b), "l"(c))
#define PACK_DUP_F32X2(d, v) \
    asm("mov.b64 %0, {%1, %1};" : "=l"(d) : "f"(v))
#define UNPACK_F32X2(lo, hi, in) \
    asm("mov.b64 {%0, %1}, %2;" : "=f"(lo), "=f"(hi) : "l"(in))
// group-scoped barrier: 4-warp (128-thread) named barrier
#define GROUP_BAR(id) \
    asm volatile("bar.sync %0, 128;" :: "r"(id) : "memory")

__global__ void prep_kernel(const float* __restrict__ Wp,
                            const float* __restrict__ Wa,
                            const float* __restrict__ ba)
{
    int tid = threadIdx.x;
    // relayout [o][t][bb][k]; mp column-normalized over k
    {
        int q8 = tid >> 4;           // o*8 + t
        int bb = (tid >> 2) & 3;
        int k  = tid & 3;
        int o  = q8 >> 3, t = q8 & 7;
        int src = o*128 + t*16 + k*4 + bb;
        float s = 0.f;
        #pragma unroll
        for (int kk = 0; kk < 4; kk++) {
            float v = Wp[o*128 + t*16 + kk*4 + bb];
            s += v * v;
        }
        float nrm = sqrtf(fmaxf(s, 1e-12f));
        g_prep[tid]       = Wp[src] / nrm;
        g_prep[512 + tid] = Wa[src];
    }
    // folded app bias: mb[(o*8+t)*4+bb] = ba[o,t] * sum_k Wa[o,t,k,bb]
    if (tid < 128) {
        int bb = tid & 3, t = (tid >> 2) & 7, o = tid >> 5;
        float sm = 0.f;
        #pragma unroll
        for (int k = 0; k < 4; k++) sm += Wa[o*128 + t*16 + k*4 + bb];
        g_prep[1024 + tid] = ba[o*8 + t] * sm;
    }
}

__global__ void __launch_bounds__(512, 2)
caps2d_fused_kernel(const float* __restrict__ inp,
                    const float* __restrict__ Wc,
                    float* __restrict__ out)
{
    extern __shared__ float smem[];
    float* in_sh   = smem;
    float* conv_sh = in_sh + IN_SH_F;
    float* wc_sh   = conv_sh + CONV_SH_F;
    float* mp_sh   = wc_sh + WC_SH_F;
    float* ma_sh   = mp_sh + MP_SH_F + MA_PAD;
    float* mb_sh   = ma_sh + MA_SH_F;

    const int tid  = threadIdx.x;
    const int warp = tid >> 5;
    const int lane = tid & 31;
    const int w0   = blockIdx.x * PXB;
    const int hh0  = blockIdx.y * ROWS;
    const int n    = blockIdx.z;

    // ---- load conv weights + prepped matrices ----
    for (int e = tid; e < 800; e += 512) wc_sh[e] = Wc[e];
    mp_sh[tid] = g_prep[tid];
    ma_sh[tid] = g_prep[512 + tid];
    if (tid < 128) mb_sh[tid] = g_prep[1024 + tid];

    // ---- vector halo load: 8 rows x 16 cols x 128 ch ----
    {
        int id  = tid & 31;          // (y,g)
        int y   = id >> 2;           // 0..7
        int g   = id & 3;            // float4 group
        int ch0 = tid >> 5;          // 0..15 ; ch = ch0 + 16*c
        int gy  = hh0 - 2 + y;
        int gx0 = w0 - 4 + g*4;
        bool ok = (gy >= 0) && (gy < HD) && (gx0 >= 0) && (gx0 + 3 < WD);
        const float* src = inp + ((n*128 + ch0)*HD + gy)*WD + gx0;
        float* dst = in_sh + ch0*CHS + y*XW + g*4;
        #pragma unroll
        for (int c = 0; c < 8; c++) {
            float4 v = make_float4(0.f, 0.f, 0.f, 0.f);
            if (ok) v = *reinterpret_cast<const float4*>(src);
            dst[0] = v.x; dst[1] = v.y; dst[2] = v.z; dst[3] = v.w;
            src += 16*HD*WD;
            dst += 16*CHS;
        }
    }
    __syncthreads();

    // routing-role constants
    const int half = warp & 1;
    const int p    = warp >> 1;
    const int gw   = w0 + p;
    const int a_   = (lane >> 2) & 3;
    const int bb   = lane & 3;
    const bool app = (lane >> 4) != 0;
    const float cx = (float)gw * (1.f/96.f);
    // conv-role constants
    const int o_c  = warp & 3;
    const int p0   = (warp >> 2) * 2;
    // pixel-pair group: conv producers {4pg..4pg+3} == routing consumers of px {2pg,2pg+1}
    const int barid = 1 + (warp >> 2);
    const unsigned FULL = 0xffffffffu;
    const bool x0 = (lane & 1) != 0;
    const bool x1 = (lane & 2) != 0;
    const bool x2 = (lane & 4) != 0;
    const bool x3 = (lane & 8) != 0;
    const int l0 = lane & 1;
    const int l1 = (lane >> 1) & 1;

    float vr[16];   // routing outputs, 4 per row, held to the epilogue

    #pragma unroll
    for (int hr = 0; hr < ROWS; hr++) {
        // ---- phase 1: depthwise 5x5 conv, packed f32x2 (j-pairs) ----
        {
            uint64_t acc2[8];        // [px(2)][jpair(4)]
            #pragma unroll
            for (int q = 0; q < 8; q++) acc2[q] = 0ull;
            const float* ib  = in_sh + (o_c*32 + lane)*CHS;
            const float* wcb = wc_sh + o_c*200;
            #pragma unroll
            for (int ky = 0; ky < 5; ky++) {
                float r[6];
                #pragma unroll
                for (int q = 0; q < 6; q++) r[q] = ib[(hr + ky)*XW + p0 + 2 + q];
                #pragma unroll
                for (int kx = 0; kx < 5; kx++) {
                    const ulonglong2 wA = *reinterpret_cast<const ulonglong2*>(wcb + (ky*5 + kx)*8);
                    const ulonglong2 wB = *reinterpret_cast<const ulonglong2*>(wcb + (ky*5 + kx)*8 + 4);
                    uint64_t va2, vb2;
                    PACK_DUP_F32X2(va2, r[kx]);
                    PACK_DUP_F32X2(vb2, r[kx + 1]);
                    FMA_F32X2(acc2[0], va2, wA.x, acc2[0]);
                    FMA_F32X2(acc2[1], va2, wA.y, acc2[1]);
                    FMA_F32X2(acc2[2], va2, wB.x, acc2[2]);
                    FMA_F32X2(acc2[3], va2, wB.y, acc2[3]);
                    FMA_F32X2(acc2[4], vb2, wA.x, acc2[4]);
                    FMA_F32X2(acc2[5], vb2, wA.y, acc2[5]);
                    FMA_F32X2(acc2[6], vb2, wB.x, acc2[6]);
                    FMA_F32X2(acc2[7], vb2, wB.y, acc2[7]);
                }
            }
            float* c0 = conv_sh + p0*(32*36)       + (o_c*8)*36 + lane;
            float* c1 = conv_sh + (p0 + 1)*(32*36) + (o_c*8)*36 + lane;
            #pragma unroll
            for (int jp = 0; jp < 4; jp++) {
                float lo, hi;
                UNPACK_F32X2(lo, hi, acc2[jp]);
                c0[(2*jp)*36]     = lo;
                c0[(2*jp + 1)*36] = hi;
            }
            #pragma unroll
            for (int jp = 0; jp < 4; jp++) {
                float lo, hi;
                UNPACK_F32X2(lo, hi, acc2[4 + jp]);
                c1[(2*jp)*36]     = lo;
                c1[(2*jp + 1)*36] = hi;
            }
        }
        GROUP_BAR(barid);   // group's conv tiles ready; role swap within group

        // ---- phase 2: u_hat[z=lane][q = o*4+tt] ----
        const float cy = (float)(hh0 + hr) * (1.f/96.f);
        float* csh = conv_sh + p * (32*36);
        float uh[16];
        #pragma unroll
        for (int o = 0; o < 4; o++) {
            #pragma unroll
            for (int tt = 0; tt < 4; tt++) {
                const int t  = half*4 + tt;
                const int j  = (app ? 4 : 0) + (t >> 1);
                const int zb = ((t & 1) << 4) + (a_ << 2);
                const float4 cv = *reinterpret_cast<const float4*>(csh + (o*8 + j)*36 + zb);
                const float* msrc = (app ? ma_sh : mp_sh) + ((o*8 + t)*4 + bb)*4;
                float4 m = *reinterpret_cast<const float4*>(msrc);
                float s0 = 0.f;
                if (app) {
                    s0 = mb_sh[(o*8 + t)*4 + bb];
                } else {
                    if (bb == 0)      m.w += cx;
                    else if (bb == 1) m.w += cy;
                }
                float s;
                s = fmaf(cv.x, m.x, s0);
                s = fmaf(cv.y, m.y, s);
                s = fmaf(cv.z, m.z, s);
                s = fmaf(cv.w, m.w, s);
                uh[o*4 + tt] = s;
            }
        }

        // ---- phase 3: dynamic routing -> vr[hr*4 + tt] ----
        float* v_ = vr + hr*4;
        float bq = 0.f;
        for (int iter = 0; iter < 3; iter++) {
            float pt[4];
            if (iter == 0) {
                #pragma unroll
                for (int tt = 0; tt < 4; tt++)
                    pt[tt] = 0.5f * (uh[tt] + uh[4 + tt] + uh[8 + tt] + uh[12 + tt]);
            } else {
                float rq = 1.f / (1.f + __expf(-bq));
                #pragma unroll
                for (int tt = 0; tt < 4; tt++) {
                    float s = 0.f;
                    #pragma unroll
                    for (int o = 0; o < 4; o++) {
                        float r = __shfl_sync(FULL, rq, (lane & 16) | (o*4 + tt));
                        s = fmaf(uh[o*4 + tt], r, s);
                    }
                    pt[tt] = s;
                }
            }
            // ---- segmented norms, merge-route butterfly: 8 shfl for all 4 tt ----
            // x[tt] = app ? pt^2 : |pt| ; OP = app ? add : max ; S[tt] over 16-half
            {
                float xv[4];
                #pragma unroll
                for (int tt = 0; tt < 4; tt++)
                    xv[tt] = app ? pt[tt]*pt[tt] : fabsf(pt[tt]);
                // L1 (d=1): keep tt with bit0 == l0
                float ka = xv[l0],      sa = xv[l0 ^ 1];
                float kb = xv[2 + l0],  sb = xv[2 + (l0 ^ 1)];
                float ra = __shfl_xor_sync(FULL, sa, 1);
                float rb = __shfl_xor_sync(FULL, sb, 1);
                float ya = app ? (ka + ra) : fmaxf(ka, ra);   // tt = l0
                float yb = app ? (kb + rb) : fmaxf(kb, rb);   // tt = 2 + l0
                // L2 (d=2): keep pair == l1 -> tt = 2*l1 + l0 = lane&3
                float kc = l1 ? yb : ya;
                float sc = l1 ? ya : yb;
                float rc = __shfl_xor_sync(FULL, sc, 2);
                float z  = app ? (kc + rc) : fmaxf(kc, rc);
                // L3,L4: reduce over 4-lane groups of the 16-half
                float z4 = __shfl_xor_sync(FULL, z, 4);
                z = app ? (z + z4) : fmaxf(z, z4);
                float z8 = __shfl_xor_sync(FULL, z, 8);
                z = app ? (z + z8) : fmaxf(z, z8);            // z = S[lane&3]
                // gather all four S back
                float w  = __shfl_xor_sync(FULL, z, 1);       // S[(lane^1)&3]
                float sE = l0 ? w : z;                        // S[2*l1]
                float sO = l0 ? z : w;                        // S[2*l1+1]
                float rE = __shfl_xor_sync(FULL, sE, 2);      // S[2*(l1^1)]
                float rO = __shfl_xor_sync(FULL, sO, 2);      // S[2*(l1^1)+1]
                float S[4];
                S[0] = l1 ? rE : sE;
                S[1] = l1 ? rO : sO;
                S[2] = l1 ? sE : rE;
                S[3] = l1 ? sO : rO;
                #pragma unroll
                for (int tt = 0; tt < 4; tt++) {
                    if (app) {
                        float x = S[tt];
                        v_[tt] = x / (1.f + x) * pt[tt] * rsqrtf(x + 1e-9f);
                    } else {
                        v_[tt] = pt[tt] / S[tt];
                    }
                }
            }
            if (iter == 2) break;

            // multi-value butterfly, 15+1 shfl
            float t8[8];
            #pragma unroll
            for (int j = 0; j < 8; j++) {
                float sa = uh[2*j]     * v_[(2*j)     & 3];
                float sb = uh[2*j + 1] * v_[(2*j + 1) & 3];
                float keep = x0 ? sb : sa;
                float send = x0 ? sa : sb;
                t8[j] = keep + __shfl_xor_sync(FULL, send, 1);
            }
            float t4[4];
            #pragma unroll
            for (int j = 0; j < 4; j++) {
                float keep = x1 ? t8[2*j + 1] : t8[2*j];
                float send = x1 ? t8[2*j]     : t8[2*j + 1];
                t4[j] = keep + __shfl_xor_sync(FULL, send, 2);
            }
            float t2[2];
            #pragma unroll
            for (int j = 0; j < 2; j++) {
                float keep = x2 ? t4[2*j + 1] : t4[2*j];
                float send = x2 ? t4[2*j]     : t4[2*j + 1];
                t2[j] = keep + __shfl_xor_sync(FULL, send, 4);
            }
            {
                float keep = x3 ? t2[1] : t2[0];
                float send = x3 ? t2[0] : t2[1];
                float R = keep + __shfl_xor_sync(FULL, send, 8);
                float other = __shfl_xor_sync(FULL, R, 16);
                bq = fmaf(R, other, bq);
            }
        }
        GROUP_BAR(barid);   // group's conv_sh reads done before next row's conv overwrites
    }

    __syncthreads();   // realign all groups before conv_sh is repurposed

    // ---- epilogue: stage all 4 rows, conv_sh reused as os[row][hr*8+p], stride 33 ----
    #pragma unroll
    for (int hr = 0; hr < ROWS; hr++)
        #pragma unroll
        for (int tt = 0; tt < 4; tt++)
            conv_sh[((half*4 + tt)*32 + lane)*33 + hr*8 + p] = vr[hr*4 + tt];
    __syncthreads();

    // ---- coalesced writeout: 16 independent STG per thread ----
    {
        int x  = tid & 7;
        int hw = (tid >> 3) & 3;
        int r0 = tid >> 5;          // 0..15
        const float* os = conv_sh + hw*8 + x;
        float* ob = out + n*256*(HD*WD) + (hh0 + hw)*WD + w0 + x;
        #pragma unroll
        for (int k = 0; k < 16; k++) {
            int row = r0 + 16*k;
            ob[row*(HD*WD)] = os[row*33];
        }
    }
}

extern "C" void kernel_launch(void* const* d_in, const int* in_sizes, int n_in,
                              void* d_out, int out_size)
{
    const float* inp = (const float*)d_in[0];   // (4,4,32,96,96)
    const float* Wc  = (const float*)d_in[1];   // (4,5,5,1,8)
    const float* Wp  = (const float*)d_in[2];   // (4,16,8)
    const float* Wa  = (const float*)d_in[3];   // (4,16,8)
    const float* ba  = (const float*)d_in[4];   // (4,8)
    float* out = (float*)d_out;                 // (4,8,32,96,96)

    // weight prep (normalization/relayout/bias-fold) once
    prep_kernel<<<1, 512>>>(Wp, Wa, ba);

    const int smem_bytes = SMEM_F * (int)sizeof(float);
    cudaFuncSetAttribute(caps2d_fused_kernel,
                         cudaFuncAttributeMaxDynamicSharedMemorySize, smem_bytes);

    dim3 grid(WD / PXB, HD / ROWS, 4);   // (12, 24, 4)
    dim3 block(512);
    caps2d_fused_kernel<<<grid, block, smem_bytes>>>(inp, Wc, out);
}

// round 13
// speedup vs baseline: 1.1871x; 1.0174x over previous
#include <cuda_runtime.h>
#include <math.h>
#include <cstdint>

// Problem constants
#define HD   96
#define WD   96
// tile
#define PXB  16     // pixels (w) per block
#define ROWS 4      // output rows per block
#define XW   24     // halo window cols [w0-4, w0+20), 4-aligned
#define CHS  193    // channel stride in floats: 8*24+1 (odd -> conflict-free lane stride)

// shared layout (floats)
#define IN_SH_F   (128*CHS)          // 24704
#define CONV_SH_F (PXB*32*36)        // 18432 : conv[p][o*8+j][z] ; epilogue: staging 256x65
#define WC_SH_F   800                // [o][ky][kx][j]
#define MP_SH_F   512                // [o][t][bb][k]  (k contiguous -> LDS.128)
#define MA_PAD    16
#define MA_SH_F   512
#define MB_SH_F   128
#define SMEM_F (IN_SH_F + CONV_SH_F + WC_SH_F + MP_SH_F + MA_PAD + MA_SH_F + MB_SH_F)

// prep scratch: [0:512) mp normalized+relayout, [512:1024) ma relayout, [1024:1152) mb
__device__ float g_prep[1152];

// Blackwell packed fp32 ops (b64 register pairs)
#define FMA_F32X2(d, a, b, c) \
    asm("fma.rn.f32x2 %0, %1, %2, %3;" : "=l"(d) : "l"(a), "l"(b), "l"(c))
#define PACK_DUP_F32X2(d, v) \
    asm("mov.b64 %0, {%1, %1};" : "=l"(d) : "f"(v))
#define UNPACK_F32X2(lo, hi, in) \
    asm("mov.b64 {%0, %1}, %2;" : "=f"(lo), "=f"(hi) : "l"(in))
// group-scoped barrier: 4-warp (128-thread) named barrier
#define GROUP_BAR(id) \
    asm volatile("bar.sync %0, 128;" :: "r"(id) : "memory")

__global__ void prep_kernel(const float* __restrict__ Wp,
                            const float* __restrict__ Wa,
                            const float* __restrict__ ba)
{
    int tid = threadIdx.x;
    // relayout [o][t][bb][k]; mp column-normalized over k
    {
        int q8 = tid >> 4;           // o*8 + t
        int bb = (tid >> 2) & 3;
        int k  = tid & 3;
        int o  = q8 >> 3, t = q8 & 7;
        int src = o*128 + t*16 + k*4 + bb;
        float s = 0.f;
        #pragma unroll
        for (int kk = 0; kk < 4; kk++) {
            float v = Wp[o*128 + t*16 + kk*4 + bb];
            s += v * v;
        }
        float nrm = sqrtf(fmaxf(s, 1e-12f));
        g_prep[tid]       = Wp[src] / nrm;
        g_prep[512 + tid] = Wa[src];
    }
    // folded app bias: mb[(o*8+t)*4+bb] = ba[o,t] * sum_k Wa[o,t,k,bb]
    if (tid < 128) {
        int bb = tid & 3, t = (tid >> 2) & 7, o = tid >> 5;
        float sm = 0.f;
        #pragma unroll
        for (int k = 0; k < 4; k++) sm += Wa[o*128 + t*16 + k*4 + bb];
        g_prep[1024 + tid] = ba[o*8 + t] * sm;
    }
}

__global__ void __launch_bounds__(1024, 1)
caps2d_fused_kernel(const float* __restrict__ inp,
                    const float* __restrict__ Wc,
                    float* __restrict__ out)
{
    extern __shared__ float smem[];
    float* in_sh   = smem;
    float* conv_sh = in_sh + IN_SH_F;
    float* wc_sh   = conv_sh + CONV_SH_F;
    float* mp_sh   = wc_sh + WC_SH_F;
    float* ma_sh   = mp_sh + MP_SH_F + MA_PAD;
    float* mb_sh   = ma_sh + MA_SH_F;

    const int tid  = threadIdx.x;
    const int warp = tid >> 5;
    const int lane = tid & 31;
    const int w0   = blockIdx.x * PXB;
    const int hh0  = blockIdx.y * ROWS;
    const int n    = blockIdx.z;

    // ---- load conv weights + prepped matrices ----
    if (tid < 800) wc_sh[tid] = Wc[tid];
    if (tid < 512) {
        mp_sh[tid] = g_prep[tid];
        ma_sh[tid] = g_prep[512 + tid];
    }
    if (tid < 128) mb_sh[tid] = g_prep[1024 + tid];

    // ---- vector halo load: 8 rows x 24 cols x 128 ch ----
    {
        int id  = tid & 63;          // (y,g): 8 rows x 6 float4 groups (48 of 64 used)
        int y   = id >> 3;           // 0..7
        int g   = id & 7;            // 0..7, valid g<6
        int ch0 = tid >> 6;          // 0..15 ; ch = ch0 + 16*c
        int gy  = hh0 - 2 + y;
        int gx0 = w0 - 4 + g*4;
        bool act = (g < 6);
        bool ok  = act && (gy >= 0) && (gy < HD) && (gx0 >= 0) && (gx0 + 3 < WD);
        const float* src = inp + ((n*128 + ch0)*HD + gy)*WD + gx0;
        float* dst = in_sh + ch0*CHS + y*XW + g*4;
        #pragma unroll
        for (int c = 0; c < 8; c++) {
            float4 v = make_float4(0.f, 0.f, 0.f, 0.f);
            if (ok) v = *reinterpret_cast<const float4*>(src);
            if (act) { dst[0] = v.x; dst[1] = v.y; dst[2] = v.z; dst[3] = v.w; }
            src += 16*HD*WD;
            dst += 16*CHS;
        }
    }
    __syncthreads();

    // routing-role constants
    const int half = warp & 1;
    const int p    = warp >> 1;          // 0..15
    const int gw   = w0 + p;
    const int a_   = (lane >> 2) & 3;
    const int bb   = lane & 3;
    const bool app = (lane >> 4) != 0;
    const float cx = (float)gw * (1.f/96.f);
    // conv-role constants
    const int o_c  = warp & 3;
    const int p0   = (warp >> 2) * 2;    // 0,2,..,14
    // pixel-pair group: conv producers {4pg..4pg+3} == routing consumers of px {2pg,2pg+1}
    const int barid = 1 + (warp >> 2);   // 1..8
    const unsigned FULL = 0xffffffffu;
    const bool x0 = (lane & 1) != 0;
    const bool x1 = (lane & 2) != 0;
    const bool x2 = (lane & 4) != 0;
    const bool x3 = (lane & 8) != 0;
    const int l0 = lane & 1;
    const int l1 = (lane >> 1) & 1;

    float vr[16];   // routing outputs, 4 per row, held to the epilogue

    #pragma unroll
    for (int hr = 0; hr < ROWS; hr++) {
        // ---- phase 1: depthwise 5x5 conv, packed f32x2 (j-pairs) ----
        {
            uint64_t acc2[8];        // [px(2)][jpair(4)]
            #pragma unroll
            for (int q = 0; q < 8; q++) acc2[q] = 0ull;
            const float* ib  = in_sh + (o_c*32 + lane)*CHS;
            const float* wcb = wc_sh + o_c*200;
            #pragma unroll
            for (int ky = 0; ky < 5; ky++) {
                float r[6];
                #pragma unroll
                for (int q = 0; q < 6; q++) r[q] = ib[(hr + ky)*XW + p0 + 2 + q];
                #pragma unroll
                for (int kx = 0; kx < 5; kx++) {
                    const ulonglong2 wA = *reinterpret_cast<const ulonglong2*>(wcb + (ky*5 + kx)*8);
                    const ulonglong2 wB = *reinterpret_cast<const ulonglong2*>(wcb + (ky*5 + kx)*8 + 4);
                    uint64_t va2, vb2;
                    PACK_DUP_F32X2(va2, r[kx]);
                    PACK_DUP_F32X2(vb2, r[kx + 1]);
                    FMA_F32X2(acc2[0], va2, wA.x, acc2[0]);
                    FMA_F32X2(acc2[1], va2, wA.y, acc2[1]);
                    FMA_F32X2(acc2[2], va2, wB.x, acc2[2]);
                    FMA_F32X2(acc2[3], va2, wB.y, acc2[3]);
                    FMA_F32X2(acc2[4], vb2, wA.x, acc2[4]);
                    FMA_F32X2(acc2[5], vb2, wA.y, acc2[5]);
                    FMA_F32X2(acc2[6], vb2, wB.x, acc2[6]);
                    FMA_F32X2(acc2[7], vb2, wB.y, acc2[7]);
                }
            }
            float* c0 = conv_sh + p0*(32*36)       + (o_c*8)*36 + lane;
            float* c1 = conv_sh + (p0 + 1)*(32*36) + (o_c*8)*36 + lane;
            #pragma unroll
            for (int jp = 0; jp < 4; jp++) {
                float lo, hi;
                UNPACK_F32X2(lo, hi, acc2[jp]);
                c0[(2*jp)*36]     = lo;
                c0[(2*jp + 1)*36] = hi;
            }
            #pragma unroll
            for (int jp = 0; jp < 4; jp++) {
                float lo, hi;
                UNPACK_F32X2(lo, hi, acc2[4 + jp]);
                c1[(2*jp)*36]     = lo;
                c1[(2*jp + 1)*36] = hi;
            }
        }
        GROUP_BAR(barid);   // group's conv tiles ready; role swap within group

        // ---- phase 2: u_hat[z=lane][q = o*4+tt] ----
        const float cy = (float)(hh0 + hr) * (1.f/96.f);
        float* csh = conv_sh + p * (32*36);
        float uh[16];
        #pragma unroll
        for (int o = 0; o < 4; o++) {
            #pragma unroll
            for (int tt = 0; tt < 4; tt++) {
                const int t  = half*4 + tt;
                const int j  = (app ? 4 : 0) + (t >> 1);
                const int zb = ((t & 1) << 4) + (a_ << 2);
                const float4 cv = *reinterpret_cast<const float4*>(csh + (o*8 + j)*36 + zb);
                const float* msrc = (app ? ma_sh : mp_sh) + ((o*8 + t)*4 + bb)*4;
                float4 m = *reinterpret_cast<const float4*>(msrc);
                float s0 = 0.f;
                if (app) {
                    s0 = mb_sh[(o*8 + t)*4 + bb];
                } else {
                    if (bb == 0)      m.w += cx;
                    else if (bb == 1) m.w += cy;
                }
                float s;
                s = fmaf(cv.x, m.x, s0);
                s = fmaf(cv.y, m.y, s);
                s = fmaf(cv.z, m.z, s);
                s = fmaf(cv.w, m.w, s);
                uh[o*4 + tt] = s;
            }
        }

        // ---- phase 3: dynamic routing -> vr[hr*4 + tt] ----
        float* v_ = vr + hr*4;
        float bq = 0.f;
        for (int iter = 0; iter < 3; iter++) {
            float pt[4];
            if (iter == 0) {
                #pragma unroll
                for (int tt = 0; tt < 4; tt++)
                    pt[tt] = 0.5f * (uh[tt] + uh[4 + tt] + uh[8 + tt] + uh[12 + tt]);
            } else {
                float rq = 1.f / (1.f + __expf(-bq));
                #pragma unroll
                for (int tt = 0; tt < 4; tt++) {
                    float s = 0.f;
                    #pragma unroll
                    for (int o = 0; o < 4; o++) {
                        float r = __shfl_sync(FULL, rq, (lane & 16) | (o*4 + tt));
                        s = fmaf(uh[o*4 + tt], r, s);
                    }
                    pt[tt] = s;
                }
            }
            // ---- segmented norms, merge-route butterfly: 8 shfl for all 4 tt ----
            {
                float xv[4];
                #pragma unroll
                for (int tt = 0; tt < 4; tt++)
                    xv[tt] = app ? pt[tt]*pt[tt] : fabsf(pt[tt]);
                float ka = xv[l0],      sa = xv[l0 ^ 1];
                float kb = xv[2 + l0],  sb = xv[2 + (l0 ^ 1)];
                float ra = __shfl_xor_sync(FULL, sa, 1);
                float rb = __shfl_xor_sync(FULL, sb, 1);
                float ya = app ? (ka + ra) : fmaxf(ka, ra);   // tt = l0
                float yb = app ? (kb + rb) : fmaxf(kb, rb);   // tt = 2 + l0
                float kc = l1 ? yb : ya;
                float sc = l1 ? ya : yb;
                float rc = __shfl_xor_sync(FULL, sc, 2);
                float z  = app ? (kc + rc) : fmaxf(kc, rc);
                float z4 = __shfl_xor_sync(FULL, z, 4);
                z = app ? (z + z4) : fmaxf(z, z4);
                float z8 = __shfl_xor_sync(FULL, z, 8);
                z = app ? (z + z8) : fmaxf(z, z8);            // z = S[lane&3]
                float w  = __shfl_xor_sync(FULL, z, 1);
                float sE = l0 ? w : z;
                float sO = l0 ? z : w;
                float rE = __shfl_xor_sync(FULL, sE, 2);
                float rO = __shfl_xor_sync(FULL, sO, 2);
                float S[4];
                S[0] = l1 ? rE : sE;
                S[1] = l1 ? rO : sO;
                S[2] = l1 ? sE : rE;
                S[3] = l1 ? sO : rO;
                #pragma unroll
                for (int tt = 0; tt < 4; tt++) {
                    if (app) {
                        float x = S[tt];
                        v_[tt] = x / (1.f + x) * pt[tt] * rsqrtf(x + 1e-9f);
                    } else {
                        v_[tt] = pt[tt] / S[tt];
                    }
                }
            }
            if (iter == 2) break;

            // multi-value butterfly, 15+1 shfl
            float t8[8];
            #pragma unroll
            for (int j = 0; j < 8; j++) {
                float sa = uh[2*j]     * v_[(2*j)     & 3];
                float sb = uh[2*j + 1] * v_[(2*j + 1) & 3];
                float keep = x0 ? sb : sa;
                float send = x0 ? sa : sb;
                t8[j] = keep + __shfl_xor_sync(FULL, send, 1);
            }
            float t4[4];
            #pragma unroll
            for (int j = 0; j < 4; j++) {
                float keep = x1 ? t8[2*j + 1] : t8[2*j];
                float send = x1 ? t8[2*j]     : t8[2*j + 1];
                t4[j] = keep + __shfl_xor_sync(FULL, send, 2);
            }
            float t2[2];
            #pragma unroll
            for (int j = 0; j < 2; j++) {
                float keep = x2 ? t4[2*j + 1] : t4[2*j];
                float send = x2 ? t4[2*j]     : t4[2*j + 1];
                t2[j] = keep + __shfl_xor_sync(FULL, send, 4);
            }
            {
                float keep = x3 ? t2[1] : t2[0];
                float send = x3 ? t2[0] : t2[1];
                float R = keep + __shfl_xor_sync(FULL, send, 8);
                float other = __shfl_xor_sync(FULL, R, 16);
                bq = fmaf(R, other, bq);
            }
        }
        GROUP_BAR(barid);   // group's conv_sh reads done before next row's conv overwrites
    }

    __syncthreads();   // realign all groups before conv_sh is repurposed

    // ---- epilogue: stage all 4 rows, conv_sh reused as os[row][hr*16+p], stride 65 ----
    #pragma unroll
    for (int hr = 0; hr < ROWS; hr++)
        #pragma unroll
        for (int tt = 0; tt < 4; tt++)
            conv_sh[((half*4 + tt)*32 + lane)*65 + hr*16 + p] = vr[hr*4 + tt];
    __syncthreads();

    // ---- coalesced writeout: 16 independent STG per thread ----
    {
        int x  = tid & 15;
        int hw = (tid >> 4) & 3;
        int r0 = tid >> 6;          // 0..15
        const float* os = conv_sh + hw*16 + x;
        float* ob = out + n*256*(HD*WD) + (hh0 + hw)*WD + w0 + x;
        #pragma unroll
        for (int k = 0; k < 16; k++) {
            int row = r0 + 16*k;
            ob[row*(HD*WD)] = os[row*65];
        }
    }
}

extern "C" void kernel_launch(void* const* d_in, const int* in_sizes, int n_in,
                              void* d_out, int out_size)
{
    const float* inp = (const float*)d_in[0];   // (4,4,32,96,96)
    const float* Wc  = (const float*)d_in[1];   // (4,5,5,1,8)
    const float* Wp  = (const float*)d_in[2];   // (4,16,8)
    const float* Wa  = (const float*)d_in[3];   // (4,16,8)
    const float* ba  = (const float*)d_in[4];   // (4,8)
    float* out = (float*)d_out;                 // (4,8,32,96,96)

    // weight prep (normalization/relayout/bias-fold) once
    prep_kernel<<<1, 512>>>(Wp, Wa, ba);

    const int smem_bytes = SMEM_F * (int)sizeof(float);
    cudaFuncSetAttribute(caps2d_fused_kernel,
                         cudaFuncAttributeMaxDynamicSharedMemorySize, smem_bytes);

    dim3 grid(WD / PXB, HD / ROWS, 4);   // (6, 24, 4)
    dim3 block(1024);
    caps2d_fused_kernel<<<grid, block, smem_bytes>>>(inp, Wc, out);
}